// round 14
// baseline (speedup 1.0000x reference)
#include <cuda_runtime.h>
#include <cstddef>

#define NN 50000
#define EE 800000
#define DD 64
#define CH 512

// array ids: 0=adjacency, 1=r-CSR, 2=c-CSR half0 (slot<mid), 3=c-CSR half1
__device__ float g_z[(size_t)EE * DD];     // 204.8 MB edge state (r-CSR slot order, in-place)
__device__ float g_y[NN * DD];
__device__ float g_dx[NN * DD];            // dis[i] * xbar[i]
__device__ float g_S[NN * DD];             // raw r-side partial
__device__ float g_S2[NN * DD];            // raw half0 c-side partial
__device__ float g_u[NN * DD];             // dis[i] * xk[i]
__device__ float g_dis[NN];

__device__ int g_cnt[4 * NN];
__device__ int g_ptrA[4 * (NN + 1)];
__device__ int g_cur[4 * NN];
__device__ int g_adj_col[2 * EE];
__device__ int g_r_lst[EE];                // slot -> other endpoint c  (edge id == slot)
__device__ int g_c_lst[EE];                // [0,mid): half0 slots; [mid,EE): half1 slots
__device__ int g_part[4 * 128];

// ---------------- precompute ----------------
__global__ void kInit(int n4) {
    int i = blockIdx.x * blockDim.x + threadIdx.x;
    if (i < n4) g_cnt[i] = 0;
}

__global__ void kCount(const int* __restrict__ src, const int* __restrict__ dst, int ne) {
    int e = blockIdx.x * blockDim.x + threadIdx.x;
    if (e >= ne) return;
    int s = src[e], d = dst[e];
    int r = s > d ? s : d;
    atomicAdd(&g_cnt[0 * NN + s], 1);
    atomicAdd(&g_cnt[0 * NN + d], 1);
    atomicAdd(&g_cnt[1 * NN + r], 1);
}

__global__ void kDis(int n) {
    int i = blockIdx.x * blockDim.x + threadIdx.x;
    if (i >= n) return;
    float x = (float)g_cnt[0 * NN + i] + 1.0f;   // degree with self loop
    float r = rsqrtf(x);
    r = r * (1.5f - 0.5f * x * r * r);
    g_dis[i] = r;
}

// scan machinery over 2 arrays starting at 'base'
__global__ void kPart(int n, int base) {
    int arr = base + blockIdx.y;
    int b = blockIdx.x;
    int t = threadIdx.x;
    int i = b * CH + t;
    __shared__ int s[CH];
    s[t] = (i < n) ? g_cnt[arr * NN + i] : 0;
    __syncthreads();
    for (int off = CH / 2; off > 0; off >>= 1) {
        if (t < off) s[t] += s[t + off];
        __syncthreads();
    }
    if (t == 0) g_part[arr * 128 + b] = s[0];
}

__global__ void kScanPart(int n, int nb, int base) {   // 256 threads: 2 segs of 128
    __shared__ int s[256];
    int t = threadIdx.x;
    int seg = t >> 7;
    int i = t & 127;
    int arr = base + seg;
    int v = (i < nb) ? g_part[arr * 128 + i] : 0;
    s[t] = v;
    __syncthreads();
    for (int off = 1; off < 128; off <<= 1) {
        int u = (i >= off) ? s[t - off] : 0;
        __syncthreads();
        s[t] += u;
        __syncthreads();
    }
    g_part[arr * 128 + i] = s[t] - v;
    if (i == nb - 1) g_ptrA[arr * (NN + 1) + n] = s[t];
}

__global__ void kWrite(int n, int base) {
    int arr = base + blockIdx.y;
    int b = blockIdx.x;
    int t = threadIdx.x;
    int i = b * CH + t;
    __shared__ int s[CH];
    int v = (i < n) ? g_cnt[arr * NN + i] : 0;
    s[t] = v;
    __syncthreads();
    for (int off = 1; off < CH; off <<= 1) {
        int u = (t >= off) ? s[t - off] : 0;
        __syncthreads();
        s[t] += u;
        __syncthreads();
    }
    if (i < n) {
        int excl = s[t] - v + g_part[arr * 128 + b];
        g_ptrA[arr * (NN + 1) + i] = excl;
        g_cur[arr * NN + i] = excl;
    }
}

__global__ void kFillR(const int* __restrict__ src, const int* __restrict__ dst, int ne) {
    int e = blockIdx.x * blockDim.x + threadIdx.x;
    if (e >= ne) return;
    int s = src[e], d = dst[e];
    int p = atomicAdd(&g_cur[0 * NN + s], 1); g_adj_col[p] = d;
    p = atomicAdd(&g_cur[0 * NN + d], 1);     g_adj_col[p] = s;
    int r = s > d ? s : d;
    int c = s > d ? d : s;
    int slot = atomicAdd(&g_cur[1 * NN + r], 1);
    g_r_lst[slot] = c;
}

// after r-CSR exists: count c-entries per half (half = slot >= mid, mid = r_ptr[ns])
__global__ void kCountC2(int ne, int ns) {
    int s = blockIdx.x * blockDim.x + threadIdx.x;
    if (s >= ne) return;
    int c = g_r_lst[s];
    int mid = g_ptrA[1 * (NN + 1) + ns];
    int half = (s >= mid) ? 1 : 0;
    atomicAdd(&g_cnt[(2 + half) * NN + c], 1);
}

__global__ void kFillC2(int ne, int ns) {
    int s = blockIdx.x * blockDim.x + threadIdx.x;
    if (s >= ne) return;
    int c = g_r_lst[s];
    int mid = g_ptrA[1 * (NN + 1) + ns];
    int half = (s >= mid) ? 1 : 0;
    int p = atomicAdd(&g_cur[(2 + half) * NN + c], 1);
    g_c_lst[(half ? mid : 0) + p] = s;
}

// ---------------- main loop kernels ----------------

// A (warp per node, float2 per lane):
// ax = sum_col u[col] + u[w];  y = 0.25*x0 + 0.75*dis*ax;  xbar = y - 0.25*S;  dx = dis*xbar
__global__ __launch_bounds__(256) void kA(const float* __restrict__ x0, int n, int first) {
    int w = (blockIdx.x * 256 + threadIdx.x) >> 5;
    int lane = threadIdx.x & 31;
    if (w >= n) return;
    int base = g_ptrA[0 * (NN + 1) + w], end = g_ptrA[0 * (NN + 1) + w + 1];
    int ofs = 2 * lane;
    float di = g_dis[w];
    float ax = 0.f, ay = 0.f;
    if (first) {
        for (int e = base; e < end; e++) {
            int col = __ldg(&g_adj_col[e]);
            float wt = __ldg(&g_dis[col]);
            float2 v = *reinterpret_cast<const float2*>(x0 + (size_t)col * DD + ofs);
            ax = fmaf(wt, v.x, ax);
            ay = fmaf(wt, v.y, ay);
        }
        float2 vs = *reinterpret_cast<const float2*>(x0 + (size_t)w * DD + ofs);
        ax = fmaf(di, vs.x, ax);
        ay = fmaf(di, vs.y, ay);
    } else {
        for (int e = base; e < end; e++) {
            int col = __ldg(&g_adj_col[e]);
            float2 v = *reinterpret_cast<const float2*>(g_u + (size_t)col * DD + ofs);
            ax += v.x;
            ay += v.y;
        }
        float2 vs = *reinterpret_cast<const float2*>(g_u + (size_t)w * DD + ofs);
        ax += vs.x;
        ay += vs.y;
    }
    float2 h = *reinterpret_cast<const float2*>(x0 + (size_t)w * DD + ofs);
    float2 yv;
    yv.x = 0.25f * h.x + 0.75f * di * ax;
    yv.y = 0.25f * h.y + 0.75f * di * ay;
    *reinterpret_cast<float2*>(g_y + (size_t)w * DD + ofs) = yv;
    float2 xb = yv;
    if (!first) {
        float2 sv = *reinterpret_cast<const float2*>(g_S + (size_t)w * DD + ofs);
        // g_S holds FINAL scaled S from previous step's kCH1
        xb.x -= 0.25f * sv.x;
        xb.y -= 0.25f * sv.y;
    }
    float2 dxv;
    dxv.x = di * xb.x;
    dxv.y = di * xb.y;
    *reinterpret_cast<float2*>(g_dx + (size_t)w * DD + ofs) = dxv;
}

// R (warp per node, nodes [lo,hi); 8-lane groups; 4 edges/iter):
//   z[s] = l21proj(z[s] + 2*(dx[w]-dx[o])) in place; raw +side partial -> g_S
__global__ __launch_bounds__(256) void kR(int lo, int hi, int first) {
    int w = lo + ((blockIdx.x * 256 + threadIdx.x) >> 5);
    int lane = threadIdx.x & 31;
    if (w >= hi) return;
    int grp = lane >> 3;
    int sub = lane & 7;
    int base = g_ptrA[1 * (NN + 1) + w], end = g_ptrA[1 * (NN + 1) + w + 1];
    const float* dwp = g_dx + (size_t)w * DD + sub * 8;
    float4 wa = *reinterpret_cast<const float4*>(dwp);
    float4 wb = *reinterpret_cast<const float4*>(dwp + 4);
    float4 sa = make_float4(0.f, 0.f, 0.f, 0.f);
    float4 sb = make_float4(0.f, 0.f, 0.f, 0.f);
    for (int s0 = base; s0 < end; s0 += 4) {
        int s = s0 + grp;
        bool act = s < end;
        int sc_ = act ? s : (end - 1);
        int o = __ldg(&g_r_lst[sc_]);
        const float* dop = g_dx + (size_t)o * DD + sub * 8;
        float4 oa = *reinterpret_cast<const float4*>(dop);
        float4 ob = *reinterpret_cast<const float4*>(dop + 4);
        float* zp = g_z + (size_t)sc_ * DD + sub * 8;
        float4 za, zb;
        za.x = 2.f * (wa.x - oa.x); za.y = 2.f * (wa.y - oa.y);
        za.z = 2.f * (wa.z - oa.z); za.w = 2.f * (wa.w - oa.w);
        zb.x = 2.f * (wb.x - ob.x); zb.y = 2.f * (wb.y - ob.y);
        zb.z = 2.f * (wb.z - ob.z); zb.w = 2.f * (wb.w - ob.w);
        if (!first) {
            float4 pa = *reinterpret_cast<const float4*>(zp);
            float4 pb = *reinterpret_cast<const float4*>(zp + 4);
            za.x += pa.x; za.y += pa.y; za.z += pa.z; za.w += pa.w;
            zb.x += pb.x; zb.y += pb.y; zb.z += pb.z; zb.w += pb.w;
        }
        float ns = za.x * za.x + za.y * za.y + za.z * za.z + za.w * za.w
                 + zb.x * zb.x + zb.y * zb.y + zb.z * zb.z + zb.w * zb.w;
        ns += __shfl_xor_sync(0xffffffffu, ns, 4);
        ns += __shfl_xor_sync(0xffffffffu, ns, 2);
        ns += __shfl_xor_sync(0xffffffffu, ns, 1);
        float rn = sqrtf(ns);
        float sc = (rn > 0.0f) ? fminf(rn, 3.0f) / rn : 0.0f;
        za.x *= sc; za.y *= sc; za.z *= sc; za.w *= sc;
        zb.x *= sc; zb.y *= sc; zb.z *= sc; zb.w *= sc;
        if (act) {
            sa.x += za.x; sa.y += za.y; sa.z += za.z; sa.w += za.w;
            sb.x += zb.x; sb.y += zb.y; sb.z += zb.z; sb.w += zb.w;
            *reinterpret_cast<float4*>(zp) = za;
            *reinterpret_cast<float4*>(zp + 4) = zb;
        }
    }
    #pragma unroll
    for (int m = 8; m <= 16; m <<= 1) {
        sa.x += __shfl_xor_sync(0xffffffffu, sa.x, m);
        sa.y += __shfl_xor_sync(0xffffffffu, sa.y, m);
        sa.z += __shfl_xor_sync(0xffffffffu, sa.z, m);
        sa.w += __shfl_xor_sync(0xffffffffu, sa.w, m);
        sb.x += __shfl_xor_sync(0xffffffffu, sb.x, m);
        sb.y += __shfl_xor_sync(0xffffffffu, sb.y, m);
        sb.z += __shfl_xor_sync(0xffffffffu, sb.z, m);
        sb.w += __shfl_xor_sync(0xffffffffu, sb.w, m);
    }
    if (grp == 0) {
        float* Sp = g_S + (size_t)w * DD + sub * 8;
        *reinterpret_cast<float4*>(Sp) = sa;
        *reinterpret_cast<float4*>(Sp + 4) = sb;
    }
}

// CH0: nodes [0,ns) gather half0 slots (L2-hot after kR(0,ns)); raw c-partial -> g_S2
__global__ __launch_bounds__(256) void kCH0(int ns) {
    int w = (blockIdx.x * 256 + threadIdx.x) >> 5;
    int lane = threadIdx.x & 31;
    if (w >= ns) return;
    int grp = lane >> 3;
    int sub = lane & 7;
    int base = g_ptrA[2 * (NN + 1) + w], end = g_ptrA[2 * (NN + 1) + w + 1];
    float4 sa = make_float4(0.f, 0.f, 0.f, 0.f);
    float4 sb = make_float4(0.f, 0.f, 0.f, 0.f);
    for (int i0 = base; i0 < end; i0 += 4) {
        int i = i0 + grp;
        if (i < end) {
            int s = __ldg(&g_c_lst[i]);
            const float* zp = g_z + (size_t)s * DD + sub * 8;
            float4 a = *reinterpret_cast<const float4*>(zp);
            float4 b = *reinterpret_cast<const float4*>(zp + 4);
            sa.x += a.x; sa.y += a.y; sa.z += a.z; sa.w += a.w;
            sb.x += b.x; sb.y += b.y; sb.z += b.z; sb.w += b.w;
        }
    }
    #pragma unroll
    for (int m = 8; m <= 16; m <<= 1) {
        sa.x += __shfl_xor_sync(0xffffffffu, sa.x, m);
        sa.y += __shfl_xor_sync(0xffffffffu, sa.y, m);
        sa.z += __shfl_xor_sync(0xffffffffu, sa.z, m);
        sa.w += __shfl_xor_sync(0xffffffffu, sa.w, m);
        sb.x += __shfl_xor_sync(0xffffffffu, sb.x, m);
        sb.y += __shfl_xor_sync(0xffffffffu, sb.y, m);
        sb.z += __shfl_xor_sync(0xffffffffu, sb.z, m);
        sb.w += __shfl_xor_sync(0xffffffffu, sb.w, m);
    }
    if (grp == 0) {
        float* Sp = g_S2 + (size_t)w * DD + sub * 8;
        *reinterpret_cast<float4*>(Sp) = sa;
        *reinterpret_cast<float4*>(Sp + 4) = sb;
    }
}

// CH1: all nodes gather half1 slots (L2-hot after kR(ns,n)); combine S2 + r-partials; finalize
__global__ __launch_bounds__(256) void kCH1(float* __restrict__ out, int n, int ns, int last) {
    int w = (blockIdx.x * 256 + threadIdx.x) >> 5;
    int lane = threadIdx.x & 31;
    if (w >= n) return;
    int grp = lane >> 3;
    int sub = lane & 7;
    int mid = g_ptrA[1 * (NN + 1) + ns];
    int base = g_ptrA[3 * (NN + 1) + w], end = g_ptrA[3 * (NN + 1) + w + 1];
    float4 sa = make_float4(0.f, 0.f, 0.f, 0.f);
    float4 sb = make_float4(0.f, 0.f, 0.f, 0.f);
    for (int i0 = base; i0 < end; i0 += 4) {
        int i = i0 + grp;
        if (i < end) {
            int s = __ldg(&g_c_lst[mid + i]);
            const float* zp = g_z + (size_t)s * DD + sub * 8;
            float4 a = *reinterpret_cast<const float4*>(zp);
            float4 b = *reinterpret_cast<const float4*>(zp + 4);
            sa.x += a.x; sa.y += a.y; sa.z += a.z; sa.w += a.w;
            sb.x += b.x; sb.y += b.y; sb.z += b.z; sb.w += b.w;
        }
    }
    #pragma unroll
    for (int m = 8; m <= 16; m <<= 1) {
        sa.x += __shfl_xor_sync(0xffffffffu, sa.x, m);
        sa.y += __shfl_xor_sync(0xffffffffu, sa.y, m);
        sa.z += __shfl_xor_sync(0xffffffffu, sa.z, m);
        sa.w += __shfl_xor_sync(0xffffffffu, sa.w, m);
        sb.x += __shfl_xor_sync(0xffffffffu, sb.x, m);
        sb.y += __shfl_xor_sync(0xffffffffu, sb.y, m);
        sb.z += __shfl_xor_sync(0xffffffffu, sb.z, m);
        sb.w += __shfl_xor_sync(0xffffffffu, sb.w, m);
    }
    if (grp == 0) {
        float di = g_dis[w];
        if (w < ns) {
            const float* S2p = g_S2 + (size_t)w * DD + sub * 8;
            float4 qa = *reinterpret_cast<const float4*>(S2p);
            float4 qb = *reinterpret_cast<const float4*>(S2p + 4);
            sa.x += qa.x; sa.y += qa.y; sa.z += qa.z; sa.w += qa.w;
            sb.x += qb.x; sb.y += qb.y; sb.z += qb.z; sb.w += qb.w;
        }
        float* Sp = g_S + (size_t)w * DD + sub * 8;
        float4 pa = *reinterpret_cast<const float4*>(Sp);
        float4 pb = *reinterpret_cast<const float4*>(Sp + 4);
        float4 Sa, Sb;
        Sa.x = di * (pa.x - sa.x); Sa.y = di * (pa.y - sa.y);
        Sa.z = di * (pa.z - sa.z); Sa.w = di * (pa.w - sa.w);
        Sb.x = di * (pb.x - sb.x); Sb.y = di * (pb.y - sb.y);
        Sb.z = di * (pb.z - sb.z); Sb.w = di * (pb.w - sb.w);
        const float* yp = g_y + (size_t)w * DD + sub * 8;
        float4 ya = *reinterpret_cast<const float4*>(yp);
        float4 yb = *reinterpret_cast<const float4*>(yp + 4);
        float4 xa, xb;
        xa.x = ya.x - 0.25f * Sa.x; xa.y = ya.y - 0.25f * Sa.y;
        xa.z = ya.z - 0.25f * Sa.z; xa.w = ya.w - 0.25f * Sa.w;
        xb.x = yb.x - 0.25f * Sb.x; xb.y = yb.y - 0.25f * Sb.y;
        xb.z = yb.z - 0.25f * Sb.z; xb.w = yb.w - 0.25f * Sb.w;
        if (last) {
            float* op = out + (size_t)w * DD + sub * 8;
            *reinterpret_cast<float4*>(op) = xa;
            *reinterpret_cast<float4*>(op + 4) = xb;
        } else {
            *reinterpret_cast<float4*>(Sp) = Sa;
            *reinterpret_cast<float4*>(Sp + 4) = Sb;
            float4 ua, ub;
            ua.x = di * xa.x; ua.y = di * xa.y; ua.z = di * xa.z; ua.w = di * xa.w;
            ub.x = di * xb.x; ub.y = di * xb.y; ub.z = di * xb.z; ub.w = di * xb.w;
            float* up = g_u + (size_t)w * DD + sub * 8;
            *reinterpret_cast<float4*>(up) = ua;
            *reinterpret_cast<float4*>(up + 4) = ub;
        }
    }
}

// ---------------- launch ----------------
extern "C" void kernel_launch(void* const* d_in, const int* in_sizes, int n_in,
                              void* d_out, int out_size) {
    (void)n_in; (void)out_size;
    const float* x0 = (const float*)d_in[0];
    const int* esrc = (const int*)d_in[1];
    const int* edst = (const int*)d_in[2];
    float* out = (float*)d_out;

    int n  = in_sizes[0] / DD;   // 50000
    int ne = in_sizes[1];        // 800000
    int ns = (int)((double)n * 0.70710678);   // slot-balanced node split
    if (ns < 1) ns = 1;
    if (ns > n) ns = n;

    const int TB = 256;
    int gI  = (4 * n + TB - 1) / TB;
    int gN  = (n + TB - 1) / TB;
    int gE  = (ne + TB - 1) / TB;
    int nb  = (n + CH - 1) / CH;
    int gW0 = (ns + 7) / 8;               // warp-per-node, nodes [0,ns)
    int gW1 = (n - ns + 7) / 8;           // nodes [ns,n)
    int gWN = (n + 7) / 8;

    // CSR builds
    kInit<<<gI, TB>>>(4 * n);
    kCount<<<gE, TB>>>(esrc, edst, ne);
    kDis<<<gN, TB>>>(n);
    kPart<<<dim3(nb, 2), CH>>>(n, 0);
    kScanPart<<<1, 256>>>(n, nb, 0);
    kWrite<<<dim3(nb, 2), CH>>>(n, 0);
    kFillR<<<gE, TB>>>(esrc, edst, ne);
    kCountC2<<<gE, TB>>>(ne, ns);
    kPart<<<dim3(nb, 2), CH>>>(n, 2);
    kScanPart<<<1, 256>>>(n, nb, 2);
    kWrite<<<dim3(nb, 2), CH>>>(n, 2);
    kFillC2<<<gE, TB>>>(ne, ns);

    const int K = 10;
    for (int k = 0; k < K; k++) {
        int first = (k == 0), last = (k == K - 1);
        kA<<<gWN, TB>>>(x0, n, first);
        kR<<<gW0, TB>>>(0, ns, first);          // half0 z RMW (L2-resident after)
        kCH0<<<gW0, TB>>>(ns);                  // gather half0 while hot
        kR<<<gW1, TB>>>(ns, n, first);          // half1 z RMW
        kCH1<<<gWN, TB>>>(out, n, ns, last);    // gather half1 while hot + finalize
    }
}

// round 15
// speedup vs baseline: 1.1300x; 1.1300x over previous
#include <cuda_runtime.h>
#include <cstddef>

#define NN 50000
#define EE 800000
#define DD 64
#define CH 512

// ---------------- static device scratch (no allocations allowed) ----------------
__device__ float g_z[(size_t)EE * DD];     // 204.8 MB edge state (R-CSR slot order, in-place)
__device__ float g_y[NN * DD];
__device__ float g_dx[NN * DD];            // dis[i] * xbar[i]
__device__ float g_S[NN * DD];             // partial (kR) then final S (kC2)
__device__ float g_u[NN * DD];             // dis[i] * xk[i]
__device__ float g_dis[NN];

__device__ int g_adj_ptr[NN + 1];
__device__ int g_adj_cur[NN];
__device__ int g_adj_col[2 * EE];
__device__ int g_r_ptr[NN + 1];
__device__ int g_r_cur[NN];
__device__ int g_r_lst[EE];                // other endpoint (c); edge id == slot index
__device__ int g_c_ptr[NN + 1];
__device__ int g_c_cur[NN];
__device__ int g_c_lst[EE];                // R-slot of that edge
__device__ int g_cnt_adj[NN];
__device__ int g_cnt_r[NN];
__device__ int g_cnt_c[NN];
__device__ int g_part[3 * 128];

// ---------------- precompute ----------------
__global__ void kInit(int n) {
    int i = blockIdx.x * blockDim.x + threadIdx.x;
    if (i < n) { g_cnt_adj[i] = 0; g_cnt_r[i] = 0; g_cnt_c[i] = 0; }
}

__global__ void kCount(const int* __restrict__ src, const int* __restrict__ dst, int ne) {
    int e = blockIdx.x * blockDim.x + threadIdx.x;
    if (e >= ne) return;
    int s = src[e], d = dst[e];
    int r = s > d ? s : d;
    int c = s > d ? d : s;
    atomicAdd(&g_cnt_adj[s], 1);
    atomicAdd(&g_cnt_adj[d], 1);
    atomicAdd(&g_cnt_r[r], 1);
    atomicAdd(&g_cnt_c[c], 1);
}

__global__ void kDis(int n) {
    int i = blockIdx.x * blockDim.x + threadIdx.x;
    if (i >= n) return;
    float x = (float)g_cnt_adj[i] + 1.0f;
    float r = rsqrtf(x);
    r = r * (1.5f - 0.5f * x * r * r);
    g_dis[i] = r;
}

__device__ __forceinline__ const int* cnt_of(int arr) {
    return arr == 0 ? g_cnt_adj : (arr == 1 ? g_cnt_r : g_cnt_c);
}
__device__ __forceinline__ int* ptr_of(int arr) {
    return arr == 0 ? g_adj_ptr : (arr == 1 ? g_r_ptr : g_c_ptr);
}
__device__ __forceinline__ int* cur_of(int arr) {
    return arr == 0 ? g_adj_cur : (arr == 1 ? g_r_cur : g_c_cur);
}

__global__ void kPart(int n) {
    int arr = blockIdx.y;
    int b = blockIdx.x;
    int t = threadIdx.x;
    int i = b * CH + t;
    __shared__ int s[CH];
    s[t] = (i < n) ? cnt_of(arr)[i] : 0;
    __syncthreads();
    for (int off = CH / 2; off > 0; off >>= 1) {
        if (t < off) s[t] += s[t + off];
        __syncthreads();
    }
    if (t == 0) g_part[arr * 128 + b] = s[0];
}

__global__ void kScanPart(int n, int nb) {
    __shared__ int s[384];
    int t = threadIdx.x;
    int arr = t >> 7;
    int i = t & 127;
    int v = (i < nb) ? g_part[arr * 128 + i] : 0;
    s[t] = v;
    __syncthreads();
    for (int off = 1; off < 128; off <<= 1) {
        int u = (i >= off) ? s[t - off] : 0;
        __syncthreads();
        s[t] += u;
        __syncthreads();
    }
    g_part[arr * 128 + i] = s[t] - v;
    if (i == nb - 1) ptr_of(arr)[n] = s[t];
}

__global__ void kWrite(int n) {
    int arr = blockIdx.y;
    int b = blockIdx.x;
    int t = threadIdx.x;
    int i = b * CH + t;
    __shared__ int s[CH];
    int v = (i < n) ? cnt_of(arr)[i] : 0;
    s[t] = v;
    __syncthreads();
    for (int off = 1; off < CH; off <<= 1) {
        int u = (t >= off) ? s[t - off] : 0;
        __syncthreads();
        s[t] += u;
        __syncthreads();
    }
    if (i < n) {
        int excl = s[t] - v + g_part[arr * 128 + b];
        ptr_of(arr)[i] = excl;
        cur_of(arr)[i] = excl;
    }
}

__global__ void kFill(const int* __restrict__ src, const int* __restrict__ dst, int ne) {
    int e = blockIdx.x * blockDim.x + threadIdx.x;
    if (e >= ne) return;
    int s = src[e], d = dst[e];
    int p = atomicAdd(&g_adj_cur[s], 1); g_adj_col[p] = d;
    p = atomicAdd(&g_adj_cur[d], 1);     g_adj_col[p] = s;
    int r = s > d ? s : d;
    int c = s > d ? d : s;
    int slot = atomicAdd(&g_r_cur[r], 1);
    g_r_lst[slot] = c;
    p = atomicAdd(&g_c_cur[c], 1);
    g_c_lst[p] = slot;
}

// ---------------- main loop kernels ----------------

// A (warp per node, float2 per lane):
// ax = sum_col u[col] + u[w];  y = 0.25*x0 + 0.75*dis*ax;  xbar = y - 0.25*S;  dx = dis*xbar
__global__ __launch_bounds__(256) void kA(const float* __restrict__ x0, int n, int first) {
    int w = (blockIdx.x * 256 + threadIdx.x) >> 5;
    int lane = threadIdx.x & 31;
    if (w >= n) return;
    int base = g_adj_ptr[w], end = g_adj_ptr[w + 1];
    int ofs = 2 * lane;
    float di = g_dis[w];
    float ax = 0.f, ay = 0.f;
    if (first) {
        for (int e = base; e < end; e++) {
            int col = __ldg(&g_adj_col[e]);
            float wt = __ldg(&g_dis[col]);
            float2 v = *reinterpret_cast<const float2*>(x0 + (size_t)col * DD + ofs);
            ax = fmaf(wt, v.x, ax);
            ay = fmaf(wt, v.y, ay);
        }
        float2 vs = *reinterpret_cast<const float2*>(x0 + (size_t)w * DD + ofs);
        ax = fmaf(di, vs.x, ax);
        ay = fmaf(di, vs.y, ay);
    } else {
        for (int e = base; e < end; e++) {
            int col = __ldg(&g_adj_col[e]);
            float2 v = *reinterpret_cast<const float2*>(g_u + (size_t)col * DD + ofs);
            ax += v.x;
            ay += v.y;
        }
        float2 vs = *reinterpret_cast<const float2*>(g_u + (size_t)w * DD + ofs);
        ax += vs.x;
        ay += vs.y;
    }
    float2 h = *reinterpret_cast<const float2*>(x0 + (size_t)w * DD + ofs);
    float2 yv;
    yv.x = 0.25f * h.x + 0.75f * di * ax;
    yv.y = 0.25f * h.y + 0.75f * di * ay;
    *reinterpret_cast<float2*>(g_y + (size_t)w * DD + ofs) = yv;
    float2 xb = yv;
    if (!first) {
        float2 sv = *reinterpret_cast<const float2*>(g_S + (size_t)w * DD + ofs);
        xb.x -= 0.25f * sv.x;
        xb.y -= 0.25f * sv.y;
    }
    float2 dxv;
    dxv.x = di * xb.x;
    dxv.y = di * xb.y;
    *reinterpret_cast<float2*>(g_dx + (size_t)w * DD + ofs) = dxv;
}

// R (warp per node; 8-lane groups; 4 edges/iter):
//   z[s] = l21proj(z[s] + 2*(dx[w]-dx[o])) in place; +side partial -> g_S.
//   z accesses are STREAMING (__ldcs/__stcs): no L2 allocation, keep node arrays resident.
__global__ __launch_bounds__(256) void kR(int n, int first) {
    int w = (blockIdx.x * 256 + threadIdx.x) >> 5;
    int lane = threadIdx.x & 31;
    if (w >= n) return;
    int grp = lane >> 3;
    int sub = lane & 7;
    int base = g_r_ptr[w], end = g_r_ptr[w + 1];
    const float* dwp = g_dx + (size_t)w * DD + sub * 8;
    float4 wa = *reinterpret_cast<const float4*>(dwp);
    float4 wb = *reinterpret_cast<const float4*>(dwp + 4);
    float4 sa = make_float4(0.f, 0.f, 0.f, 0.f);
    float4 sb = make_float4(0.f, 0.f, 0.f, 0.f);
    for (int s0 = base; s0 < end; s0 += 4) {
        int s = s0 + grp;
        bool act = s < end;
        int sc_ = act ? s : (end - 1);
        int o = __ldg(&g_r_lst[sc_]);
        const float* dop = g_dx + (size_t)o * DD + sub * 8;
        float4 oa = *reinterpret_cast<const float4*>(dop);
        float4 ob = *reinterpret_cast<const float4*>(dop + 4);
        float* zp = g_z + (size_t)sc_ * DD + sub * 8;
        float4 za, zb;
        za.x = 2.f * (wa.x - oa.x); za.y = 2.f * (wa.y - oa.y);
        za.z = 2.f * (wa.z - oa.z); za.w = 2.f * (wa.w - oa.w);
        zb.x = 2.f * (wb.x - ob.x); zb.y = 2.f * (wb.y - ob.y);
        zb.z = 2.f * (wb.z - ob.z); zb.w = 2.f * (wb.w - ob.w);
        if (!first) {
            float4 pa = __ldcs(reinterpret_cast<const float4*>(zp));
            float4 pb = __ldcs(reinterpret_cast<const float4*>(zp + 4));
            za.x += pa.x; za.y += pa.y; za.z += pa.z; za.w += pa.w;
            zb.x += pb.x; zb.y += pb.y; zb.z += pb.z; zb.w += pb.w;
        }
        float ns = za.x * za.x + za.y * za.y + za.z * za.z + za.w * za.w
                 + zb.x * zb.x + zb.y * zb.y + zb.z * zb.z + zb.w * zb.w;
        ns += __shfl_xor_sync(0xffffffffu, ns, 4);
        ns += __shfl_xor_sync(0xffffffffu, ns, 2);
        ns += __shfl_xor_sync(0xffffffffu, ns, 1);
        float rn = sqrtf(ns);
        float sc = (rn > 0.0f) ? fminf(rn, 3.0f) / rn : 0.0f;
        za.x *= sc; za.y *= sc; za.z *= sc; za.w *= sc;
        zb.x *= sc; zb.y *= sc; zb.z *= sc; zb.w *= sc;
        if (act) {
            sa.x += za.x; sa.y += za.y; sa.z += za.z; sa.w += za.w;
            sb.x += zb.x; sb.y += zb.y; sb.z += zb.z; sb.w += zb.w;
            __stcs(reinterpret_cast<float4*>(zp), za);
            __stcs(reinterpret_cast<float4*>(zp + 4), zb);
        }
    }
    #pragma unroll
    for (int m = 8; m <= 16; m <<= 1) {
        sa.x += __shfl_xor_sync(0xffffffffu, sa.x, m);
        sa.y += __shfl_xor_sync(0xffffffffu, sa.y, m);
        sa.z += __shfl_xor_sync(0xffffffffu, sa.z, m);
        sa.w += __shfl_xor_sync(0xffffffffu, sa.w, m);
        sb.x += __shfl_xor_sync(0xffffffffu, sb.x, m);
        sb.y += __shfl_xor_sync(0xffffffffu, sb.y, m);
        sb.z += __shfl_xor_sync(0xffffffffu, sb.z, m);
        sb.w += __shfl_xor_sync(0xffffffffu, sb.w, m);
    }
    if (grp == 0) {
        float* Sp = g_S + (size_t)w * DD + sub * 8;
        *reinterpret_cast<float4*>(Sp) = sa;
        *reinterpret_cast<float4*>(Sp + 4) = sb;
    }
}

// C2 (warp per node; 8-lane groups): gather -side z rows (streaming), finalize S, xk, u
__global__ __launch_bounds__(256) void kC2(float* __restrict__ out, int n, int last) {
    int w = (blockIdx.x * 256 + threadIdx.x) >> 5;
    int lane = threadIdx.x & 31;
    if (w >= n) return;
    int grp = lane >> 3;
    int sub = lane & 7;
    int base = g_c_ptr[w], end = g_c_ptr[w + 1];
    float4 sa = make_float4(0.f, 0.f, 0.f, 0.f);
    float4 sb = make_float4(0.f, 0.f, 0.f, 0.f);
    for (int i0 = base; i0 < end; i0 += 4) {
        int i = i0 + grp;
        if (i < end) {
            int s = __ldg(&g_c_lst[i]);
            const float* zp = g_z + (size_t)s * DD + sub * 8;
            float4 a = __ldcs(reinterpret_cast<const float4*>(zp));
            float4 b = __ldcs(reinterpret_cast<const float4*>(zp + 4));
            sa.x += a.x; sa.y += a.y; sa.z += a.z; sa.w += a.w;
            sb.x += b.x; sb.y += b.y; sb.z += b.z; sb.w += b.w;
        }
    }
    #pragma unroll
    for (int m = 8; m <= 16; m <<= 1) {
        sa.x += __shfl_xor_sync(0xffffffffu, sa.x, m);
        sa.y += __shfl_xor_sync(0xffffffffu, sa.y, m);
        sa.z += __shfl_xor_sync(0xffffffffu, sa.z, m);
        sa.w += __shfl_xor_sync(0xffffffffu, sa.w, m);
        sb.x += __shfl_xor_sync(0xffffffffu, sb.x, m);
        sb.y += __shfl_xor_sync(0xffffffffu, sb.y, m);
        sb.z += __shfl_xor_sync(0xffffffffu, sb.z, m);
        sb.w += __shfl_xor_sync(0xffffffffu, sb.w, m);
    }
    if (grp == 0) {
        float di = g_dis[w];
        float* Sp = g_S + (size_t)w * DD + sub * 8;
        float4 pa = *reinterpret_cast<const float4*>(Sp);
        float4 pb = *reinterpret_cast<const float4*>(Sp + 4);
        float4 Sa, Sb;
        Sa.x = di * (pa.x - sa.x); Sa.y = di * (pa.y - sa.y);
        Sa.z = di * (pa.z - sa.z); Sa.w = di * (pa.w - sa.w);
        Sb.x = di * (pb.x - sb.x); Sb.y = di * (pb.y - sb.y);
        Sb.z = di * (pb.z - sb.z); Sb.w = di * (pb.w - sb.w);
        const float* yp = g_y + (size_t)w * DD + sub * 8;
        float4 ya = *reinterpret_cast<const float4*>(yp);
        float4 yb = *reinterpret_cast<const float4*>(yp + 4);
        float4 xa, xb;
        xa.x = ya.x - 0.25f * Sa.x; xa.y = ya.y - 0.25f * Sa.y;
        xa.z = ya.z - 0.25f * Sa.z; xa.w = ya.w - 0.25f * Sa.w;
        xb.x = yb.x - 0.25f * Sb.x; xb.y = yb.y - 0.25f * Sb.y;
        xb.z = yb.z - 0.25f * Sb.z; xb.w = yb.w - 0.25f * Sb.w;
        if (last) {
            float* op = out + (size_t)w * DD + sub * 8;
            *reinterpret_cast<float4*>(op) = xa;
            *reinterpret_cast<float4*>(op + 4) = xb;
        } else {
            *reinterpret_cast<float4*>(Sp) = Sa;
            *reinterpret_cast<float4*>(Sp + 4) = Sb;
            float4 ua, ub;
            ua.x = di * xa.x; ua.y = di * xa.y; ua.z = di * xa.z; ua.w = di * xa.w;
            ub.x = di * xb.x; ub.y = di * xb.y; ub.z = di * xb.z; ub.w = di * xb.w;
            float* up = g_u + (size_t)w * DD + sub * 8;
            *reinterpret_cast<float4*>(up) = ua;
            *reinterpret_cast<float4*>(up + 4) = ub;
        }
    }
}

// ---------------- launch ----------------
extern "C" void kernel_launch(void* const* d_in, const int* in_sizes, int n_in,
                              void* d_out, int out_size) {
    (void)n_in; (void)out_size;
    const float* x0 = (const float*)d_in[0];
    const int* esrc = (const int*)d_in[1];
    const int* edst = (const int*)d_in[2];
    float* out = (float*)d_out;

    int n  = in_sizes[0] / DD;   // 50000
    int ne = in_sizes[1];        // 800000

    const int TB = 256;
    int gN  = (n + TB - 1) / TB;
    int gE  = (ne + TB - 1) / TB;
    int gWN = (n + 7) / 8;
    int nb  = (n + CH - 1) / CH;

    kInit<<<gN, TB>>>(n);
    kCount<<<gE, TB>>>(esrc, edst, ne);
    kDis<<<gN, TB>>>(n);
    kPart<<<dim3(nb, 3), CH>>>(n);
    kScanPart<<<1, 384>>>(n, nb);
    kWrite<<<dim3(nb, 3), CH>>>(n);
    kFill<<<gE, TB>>>(esrc, edst, ne);

    const int K = 10;
    for (int k = 0; k < K; k++) {
        kA<<<gWN, TB>>>(x0, n, k == 0);
        kR<<<gWN, TB>>>(n, k == 0);
        kC2<<<gWN, TB>>>(out, n, k == K - 1);
    }
}

// round 17
// speedup vs baseline: 1.1593x; 1.0260x over previous
#include <cuda_runtime.h>
#include <cstddef>

#define NN 50000
#define EE 800000
#define DD 64
#define CH 512

// array ids: 0 = r-CSR (slot owner = max endpoint), 1 = c-CSR (min endpoint)
__device__ float g_z[(size_t)EE * DD];     // 204.8 MB edge state (r-CSR slot order, in-place)
__device__ float g_y[NN * DD];
__device__ float g_dx[NN * DD];            // dis[i] * xbar[i]
__device__ float g_S[NN * DD];             // partial (kR) then final S (kC2)
__device__ float g_u[NN * DD];             // dis[i] * xk[i]
__device__ float g_dis[NN];

__device__ int g_cnt[2 * NN];
__device__ int g_ptrA[2 * (NN + 1)];
__device__ int g_cur[2 * NN];
__device__ int g_r_lst[EE];                // slot -> other endpoint (c); edge id == slot
__device__ int g_c_lst[EE];                // c-entry -> slot
__device__ int g_c_nbr[EE];                // c-entry -> neighbor (r)   [adjacency replacement]
__device__ int g_part[2 * 128];

// ---------------- precompute ----------------
__global__ void kInit(int n2) {
    int i = blockIdx.x * blockDim.x + threadIdx.x;
    if (i < n2) g_cnt[i] = 0;
}

__global__ void kCount(const int* __restrict__ src, const int* __restrict__ dst, int ne) {
    int e = blockIdx.x * blockDim.x + threadIdx.x;
    if (e >= ne) return;
    int s = src[e], d = dst[e];
    int r = s > d ? s : d;
    int c = s > d ? d : s;
    atomicAdd(&g_cnt[0 * NN + r], 1);
    atomicAdd(&g_cnt[1 * NN + c], 1);
}

__global__ void kDis(int n) {
    int i = blockIdx.x * blockDim.x + threadIdx.x;
    if (i >= n) return;
    float x = (float)(g_cnt[0 * NN + i] + g_cnt[1 * NN + i]) + 1.0f;  // degree + self loop
    float r = rsqrtf(x);
    r = r * (1.5f - 0.5f * x * r * r);
    g_dis[i] = r;
}

__global__ void kPart(int n) {
    int arr = blockIdx.y;
    int b = blockIdx.x;
    int t = threadIdx.x;
    int i = b * CH + t;
    __shared__ int s[CH];
    s[t] = (i < n) ? g_cnt[arr * NN + i] : 0;
    __syncthreads();
    for (int off = CH / 2; off > 0; off >>= 1) {
        if (t < off) s[t] += s[t + off];
        __syncthreads();
    }
    if (t == 0) g_part[arr * 128 + b] = s[0];
}

__global__ void kScanPart(int n, int nb) {   // 256 threads: 2 segments of 128
    __shared__ int s[256];
    int t = threadIdx.x;
    int arr = t >> 7;
    int i = t & 127;
    int v = (i < nb) ? g_part[arr * 128 + i] : 0;
    s[t] = v;
    __syncthreads();
    for (int off = 1; off < 128; off <<= 1) {
        int u = (i >= off) ? s[t - off] : 0;
        __syncthreads();
        s[t] += u;
        __syncthreads();
    }
    g_part[arr * 128 + i] = s[t] - v;
    if (i == nb - 1) g_ptrA[arr * (NN + 1) + n] = s[t];
}

__global__ void kWrite(int n) {
    int arr = blockIdx.y;
    int b = blockIdx.x;
    int t = threadIdx.x;
    int i = b * CH + t;
    __shared__ int s[CH];
    int v = (i < n) ? g_cnt[arr * NN + i] : 0;
    s[t] = v;
    __syncthreads();
    for (int off = 1; off < CH; off <<= 1) {
        int u = (t >= off) ? s[t - off] : 0;
        __syncthreads();
        s[t] += u;
        __syncthreads();
    }
    if (i < n) {
        int excl = s[t] - v + g_part[arr * 128 + b];
        g_ptrA[arr * (NN + 1) + i] = excl;
        g_cur[arr * NN + i] = excl;
    }
}

__global__ void kFill(const int* __restrict__ src, const int* __restrict__ dst, int ne) {
    int e = blockIdx.x * blockDim.x + threadIdx.x;
    if (e >= ne) return;
    int s = src[e], d = dst[e];
    int r = s > d ? s : d;
    int c = s > d ? d : s;
    int slot = atomicAdd(&g_cur[0 * NN + r], 1);
    g_r_lst[slot] = c;
    int p = atomicAdd(&g_cur[1 * NN + c], 1);
    g_c_lst[p] = slot;
    g_c_nbr[p] = r;
}

// ---------------- main loop kernels ----------------

// A (warp per node, float2 per lane):
// ax = sum over r-list + c-list of u[nbr] + u[w];  y = 0.25*x0 + 0.75*dis*ax;
// xbar = y - 0.25*S;  dx = dis*xbar
__global__ __launch_bounds__(256) void kA(const float* __restrict__ x0, int n, int first) {
    int w = (blockIdx.x * 256 + threadIdx.x) >> 5;
    int lane = threadIdx.x & 31;
    if (w >= n) return;
    int rb = g_ptrA[0 * (NN + 1) + w], re = g_ptrA[0 * (NN + 1) + w + 1];
    int cb = g_ptrA[1 * (NN + 1) + w], ce = g_ptrA[1 * (NN + 1) + w + 1];
    int ofs = 2 * lane;
    float di = g_dis[w];
    float ax = 0.f, ay = 0.f;
    if (first) {
        for (int e = rb; e < re; e++) {
            int col = __ldg(&g_r_lst[e]);
            float wt = __ldg(&g_dis[col]);
            float2 v = *reinterpret_cast<const float2*>(x0 + (size_t)col * DD + ofs);
            ax = fmaf(wt, v.x, ax);
            ay = fmaf(wt, v.y, ay);
        }
        for (int e = cb; e < ce; e++) {
            int col = __ldg(&g_c_nbr[e]);
            float wt = __ldg(&g_dis[col]);
            float2 v = *reinterpret_cast<const float2*>(x0 + (size_t)col * DD + ofs);
            ax = fmaf(wt, v.x, ax);
            ay = fmaf(wt, v.y, ay);
        }
        float2 vs = *reinterpret_cast<const float2*>(x0 + (size_t)w * DD + ofs);
        ax = fmaf(di, vs.x, ax);
        ay = fmaf(di, vs.y, ay);
    } else {
        for (int e = rb; e < re; e++) {
            int col = __ldg(&g_r_lst[e]);
            float2 v = *reinterpret_cast<const float2*>(g_u + (size_t)col * DD + ofs);
            ax += v.x;
            ay += v.y;
        }
        for (int e = cb; e < ce; e++) {
            int col = __ldg(&g_c_nbr[e]);
            float2 v = *reinterpret_cast<const float2*>(g_u + (size_t)col * DD + ofs);
            ax += v.x;
            ay += v.y;
        }
        float2 vs = *reinterpret_cast<const float2*>(g_u + (size_t)w * DD + ofs);
        ax += vs.x;
        ay += vs.y;
    }
    float2 h = *reinterpret_cast<const float2*>(x0 + (size_t)w * DD + ofs);
    float2 yv;
    yv.x = 0.25f * h.x + 0.75f * di * ax;
    yv.y = 0.25f * h.y + 0.75f * di * ay;
    *reinterpret_cast<float2*>(g_y + (size_t)w * DD + ofs) = yv;
    float2 xb = yv;
    if (!first) {
        float2 sv = *reinterpret_cast<const float2*>(g_S + (size_t)w * DD + ofs);
        xb.x -= 0.25f * sv.x;
        xb.y -= 0.25f * sv.y;
    }
    float2 dxv;
    dxv.x = di * xb.x;
    dxv.y = di * xb.y;
    *reinterpret_cast<float2*>(g_dx + (size_t)w * DD + ofs) = dxv;
}

// R (warp per node; 8-lane groups; 4 edges/iter):
//   z[s] = l21proj(z[s] + 2*(dx[w]-dx[o])) in place; +side partial -> g_S.
//   z accesses are STREAMING (__ldcs/__stcs): no L2 allocation, keep node arrays resident.
__global__ __launch_bounds__(256) void kR(int n, int first) {
    int w = (blockIdx.x * 256 + threadIdx.x) >> 5;
    int lane = threadIdx.x & 31;
    if (w >= n) return;
    int grp = lane >> 3;
    int sub = lane & 7;
    int base = g_ptrA[0 * (NN + 1) + w], end = g_ptrA[0 * (NN + 1) + w + 1];
    const float* dwp = g_dx + (size_t)w * DD + sub * 8;
    float4 wa = *reinterpret_cast<const float4*>(dwp);
    float4 wb = *reinterpret_cast<const float4*>(dwp + 4);
    float4 sa = make_float4(0.f, 0.f, 0.f, 0.f);
    float4 sb = make_float4(0.f, 0.f, 0.f, 0.f);
    for (int s0 = base; s0 < end; s0 += 4) {
        int s = s0 + grp;
        bool act = s < end;
        int sc_ = act ? s : (end - 1);
        int o = __ldg(&g_r_lst[sc_]);
        const float* dop = g_dx + (size_t)o * DD + sub * 8;
        float4 oa = *reinterpret_cast<const float4*>(dop);
        float4 ob = *reinterpret_cast<const float4*>(dop + 4);
        float* zp = g_z + (size_t)sc_ * DD + sub * 8;
        float4 za, zb;
        za.x = 2.f * (wa.x - oa.x); za.y = 2.f * (wa.y - oa.y);
        za.z = 2.f * (wa.z - oa.z); za.w = 2.f * (wa.w - oa.w);
        zb.x = 2.f * (wb.x - ob.x); zb.y = 2.f * (wb.y - ob.y);
        zb.z = 2.f * (wb.z - ob.z); zb.w = 2.f * (wb.w - ob.w);
        if (!first) {
            float4 pa = __ldcs(reinterpret_cast<const float4*>(zp));
            float4 pb = __ldcs(reinterpret_cast<const float4*>(zp + 4));
            za.x += pa.x; za.y += pa.y; za.z += pa.z; za.w += pa.w;
            zb.x += pb.x; zb.y += pb.y; zb.z += pb.z; zb.w += pb.w;
        }
        float ns = za.x * za.x + za.y * za.y + za.z * za.z + za.w * za.w
                 + zb.x * zb.x + zb.y * zb.y + zb.z * zb.z + zb.w * zb.w;
        ns += __shfl_xor_sync(0xffffffffu, ns, 4);
        ns += __shfl_xor_sync(0xffffffffu, ns, 2);
        ns += __shfl_xor_sync(0xffffffffu, ns, 1);
        float rn = sqrtf(ns);
        float sc = (rn > 0.0f) ? fminf(rn, 3.0f) / rn : 0.0f;
        za.x *= sc; za.y *= sc; za.z *= sc; za.w *= sc;
        zb.x *= sc; zb.y *= sc; zb.z *= sc; zb.w *= sc;
        if (act) {
            sa.x += za.x; sa.y += za.y; sa.z += za.z; sa.w += za.w;
            sb.x += zb.x; sb.y += zb.y; sb.z += zb.z; sb.w += zb.w;
            __stcs(reinterpret_cast<float4*>(zp), za);
            __stcs(reinterpret_cast<float4*>(zp + 4), zb);
        }
    }
    #pragma unroll
    for (int m = 8; m <= 16; m <<= 1) {
        sa.x += __shfl_xor_sync(0xffffffffu, sa.x, m);
        sa.y += __shfl_xor_sync(0xffffffffu, sa.y, m);
        sa.z += __shfl_xor_sync(0xffffffffu, sa.z, m);
        sa.w += __shfl_xor_sync(0xffffffffu, sa.w, m);
        sb.x += __shfl_xor_sync(0xffffffffu, sb.x, m);
        sb.y += __shfl_xor_sync(0xffffffffu, sb.y, m);
        sb.z += __shfl_xor_sync(0xffffffffu, sb.z, m);
        sb.w += __shfl_xor_sync(0xffffffffu, sb.w, m);
    }
    if (grp == 0) {
        float* Sp = g_S + (size_t)w * DD + sub * 8;
        *reinterpret_cast<float4*>(Sp) = sa;
        *reinterpret_cast<float4*>(Sp + 4) = sb;
    }
}

// C2 (warp per node; 8-lane groups): gather -side z rows (streaming), finalize S, xk, u
__global__ __launch_bounds__(256) void kC2(float* __restrict__ out, int n, int last) {
    int w = (blockIdx.x * 256 + threadIdx.x) >> 5;
    int lane = threadIdx.x & 31;
    if (w >= n) return;
    int grp = lane >> 3;
    int sub = lane & 7;
    int base = g_ptrA[1 * (NN + 1) + w], end = g_ptrA[1 * (NN + 1) + w + 1];
    float4 sa = make_float4(0.f, 0.f, 0.f, 0.f);
    float4 sb = make_float4(0.f, 0.f, 0.f, 0.f);
    for (int i0 = base; i0 < end; i0 += 4) {
        int i = i0 + grp;
        if (i < end) {
            int s = __ldg(&g_c_lst[i]);
            const float* zp = g_z + (size_t)s * DD + sub * 8;
            float4 a = __ldcs(reinterpret_cast<const float4*>(zp));
            float4 b = __ldcs(reinterpret_cast<const float4*>(zp + 4));
            sa.x += a.x; sa.y += a.y; sa.z += a.z; sa.w += a.w;
            sb.x += b.x; sb.y += b.y; sb.z += b.z; sb.w += b.w;
        }
    }
    #pragma unroll
    for (int m = 8; m <= 16; m <<= 1) {
        sa.x += __shfl_xor_sync(0xffffffffu, sa.x, m);
        sa.y += __shfl_xor_sync(0xffffffffu, sa.y, m);
        sa.z += __shfl_xor_sync(0xffffffffu, sa.z, m);
        sa.w += __shfl_xor_sync(0xffffffffu, sa.w, m);
        sb.x += __shfl_xor_sync(0xffffffffu, sb.x, m);
        sb.y += __shfl_xor_sync(0xffffffffu, sb.y, m);
        sb.z += __shfl_xor_sync(0xffffffffu, sb.z, m);
        sb.w += __shfl_xor_sync(0xffffffffu, sb.w, m);
    }
    if (grp == 0) {
        float di = g_dis[w];
        float* Sp = g_S + (size_t)w * DD + sub * 8;
        float4 pa = *reinterpret_cast<const float4*>(Sp);
        float4 pb = *reinterpret_cast<const float4*>(Sp + 4);
        float4 Sa, Sb;
        Sa.x = di * (pa.x - sa.x); Sa.y = di * (pa.y - sa.y);
        Sa.z = di * (pa.z - sa.z); Sa.w = di * (pa.w - sa.w);
        Sb.x = di * (pb.x - sb.x); Sb.y = di * (pb.y - sb.y);
        Sb.z = di * (pb.z - sb.z); Sb.w = di * (pb.w - sb.w);
        const float* yp = g_y + (size_t)w * DD + sub * 8;
        float4 ya = *reinterpret_cast<const float4*>(yp);
        float4 yb = *reinterpret_cast<const float4*>(yp + 4);
        float4 xa, xb;
        xa.x = ya.x - 0.25f * Sa.x; xa.y = ya.y - 0.25f * Sa.y;
        xa.z = ya.z - 0.25f * Sa.z; xa.w = ya.w - 0.25f * Sa.w;
        xb.x = yb.x - 0.25f * Sb.x; xb.y = yb.y - 0.25f * Sb.y;
        xb.z = yb.z - 0.25f * Sb.z; xb.w = yb.w - 0.25f * Sb.w;
        if (last) {
            float* op = out + (size_t)w * DD + sub * 8;
            *reinterpret_cast<float4*>(op) = xa;
            *reinterpret_cast<float4*>(op + 4) = xb;
        } else {
            *reinterpret_cast<float4*>(Sp) = Sa;
            *reinterpret_cast<float4*>(Sp + 4) = Sb;
            float4 ua, ub;
            ua.x = di * xa.x; ua.y = di * xa.y; ua.z = di * xa.z; ua.w = di * xa.w;
            ub.x = di * xb.x; ub.y = di * xb.y; ub.z = di * xb.z; ub.w = di * xb.w;
            float* up = g_u + (size_t)w * DD + sub * 8;
            *reinterpret_cast<float4*>(up) = ua;
            *reinterpret_cast<float4*>(up + 4) = ub;
        }
    }
}

// ---------------- launch ----------------
extern "C" void kernel_launch(void* const* d_in, const int* in_sizes, int n_in,
                              void* d_out, int out_size) {
    (void)n_in; (void)out_size;
    const float* x0 = (const float*)d_in[0];
    const int* esrc = (const int*)d_in[1];
    const int* edst = (const int*)d_in[2];
    float* out = (float*)d_out;

    int n  = in_sizes[0] / DD;   // 50000
    int ne = in_sizes[1];        // 800000

    const int TB = 256;
    int gI  = (2 * n + TB - 1) / TB;
    int gN  = (n + TB - 1) / TB;
    int gE  = (ne + TB - 1) / TB;
    int gWN = (n + 7) / 8;
    int nb  = (n + CH - 1) / CH;

    kInit<<<gI, TB>>>(2 * n);
    kCount<<<gE, TB>>>(esrc, edst, ne);
    kDis<<<gN, TB>>>(n);
    kPart<<<dim3(nb, 2), CH>>>(n);
    kScanPart<<<1, 256>>>(n, nb);
    kWrite<<<dim3(nb, 2), CH>>>(n);
    kFill<<<gE, TB>>>(esrc, edst, ne);

    const int K = 10;
    for (int k = 0; k < K; k++) {
        kA<<<gWN, TB>>>(x0, n, k == 0);
        kR<<<gWN, TB>>>(n, k == 0);
        kC2<<<gWN, TB>>>(out, n, k == K - 1);
    }
}